// round 2
// baseline (speedup 1.0000x reference)
#include <cuda_runtime.h>
#include <cstdint>

#define N_NODES 100000
#define N_EDGES 1600000
#define FEAT 128

// Scratch (static device globals — no allocation).
__device__ float g_xw[(size_t)N_NODES * FEAT];   // 51.2 MB
__device__ float g_deg[N_NODES];
__device__ float g_dis[N_NODES];
__device__ int   g_is64;

// ---------------------------------------------------------------------------
// Detect whether edge_index arrived as int64 or int32.
// Values are node ids < 100000, so for int64 (little-endian) every odd 32-bit
// word is 0. Probability of 64 consecutive zero odd-words under int32 ~ 0.
// ---------------------------------------------------------------------------
__global__ void detect_kernel(const unsigned int* __restrict__ w) {
    int is64 = 1;
    for (int i = 0; i < 64; i++) {
        if (w[2 * i + 1] != 0u) { is64 = 0; break; }
    }
    g_is64 = is64;
}

__device__ __forceinline__ long long edge_at(const void* p, long long i) {
    if (g_is64) return ((const long long*)p)[i];
    return (long long)((const int*)p)[i];
}

// ---------------------------------------------------------------------------
// Degree pipeline
// ---------------------------------------------------------------------------
__global__ void zero_deg_kernel() {
    int i = blockIdx.x * blockDim.x + threadIdx.x;
    if (i < N_NODES) g_deg[i] = 0.0f;
}

__global__ void count_kernel(const void* __restrict__ ei) {
    int e = blockIdx.x * blockDim.x + threadIdx.x;
    if (e >= N_EDGES) return;
    long long c = edge_at(ei, (long long)N_EDGES + e);  // col = targets
    atomicAdd(&g_deg[c], 1.0f);
}

__global__ void rsqrt_kernel() {
    int i = blockIdx.x * blockDim.x + threadIdx.x;
    if (i < N_NODES) g_dis[i] = rsqrtf(g_deg[i] + 1.0f);  // +1 self-loop
}

// ---------------------------------------------------------------------------
// GEMM: xw = x @ W, epilogue writes g_xw and initializes
//   out = xw * dis^2 (self-loop message) + b
// 128x128 block tile, 256 threads, 8x8 per-thread register tile, BK=16.
// ---------------------------------------------------------------------------
__global__ __launch_bounds__(256) void gemm_kernel(
    const float* __restrict__ x, const float* __restrict__ W,
    const float* __restrict__ b, float* __restrict__ out)
{
    __shared__ float xs[16][128];   // [k][row] (transposed)
    __shared__ float ws[16][128];   // [k][col]

    const int tid = threadIdx.x;
    const int tx = tid & 15;        // col group 0..15 -> cols tx*8..tx*8+7
    const int ty = tid >> 4;        // row group 0..15 -> rows ty*8..ty*8+7
    const int row0 = blockIdx.x * 128;

    float acc[8][8];
    #pragma unroll
    for (int i = 0; i < 8; i++)
        #pragma unroll
        for (int j = 0; j < 8; j++) acc[i][j] = 0.0f;

    const int lr  = tid >> 2;       // 0..63  (x-tile row within half)
    const int lc4 = tid & 3;        // 0..3   (which float4 in the 16-wide k slab)

    for (int k0 = 0; k0 < FEAT; k0 += 16) {
        // x tile: 128 rows x 16 k, two 64-row passes, float4 loads
        #pragma unroll
        for (int p = 0; p < 2; p++) {
            int r  = lr + p * 64;
            int gr = row0 + r;
            float4 v = make_float4(0.f, 0.f, 0.f, 0.f);
            if (gr < N_NODES)
                v = *(const float4*)(x + (size_t)gr * FEAT + k0 + lc4 * 4);
            xs[lc4 * 4 + 0][r] = v.x;
            xs[lc4 * 4 + 1][r] = v.y;
            xs[lc4 * 4 + 2][r] = v.z;
            xs[lc4 * 4 + 3][r] = v.w;
        }
        // W tile: 16 k x 128 cols
        #pragma unroll
        for (int p = 0; p < 2; p++) {
            int idx = tid + p * 256;
            int kr  = idx >> 5;     // 0..15
            int c4  = idx & 31;     // 0..31
            *(float4*)&ws[kr][c4 * 4] =
                *(const float4*)(W + (size_t)(k0 + kr) * FEAT + c4 * 4);
        }
        __syncthreads();

        #pragma unroll
        for (int kk = 0; kk < 16; kk++) {
            float a[8], w[8];
            #pragma unroll
            for (int i = 0; i < 8; i++) a[i] = xs[kk][ty * 8 + i];
            #pragma unroll
            for (int j = 0; j < 8; j++) w[j] = ws[kk][tx * 8 + j];
            #pragma unroll
            for (int i = 0; i < 8; i++)
                #pragma unroll
                for (int j = 0; j < 8; j++)
                    acc[i][j] = fmaf(a[i], w[j], acc[i][j]);
        }
        __syncthreads();
    }

    // Epilogue: write xw, init out = xw*dis^2 + b
    #pragma unroll
    for (int i = 0; i < 8; i++) {
        int gr = row0 + ty * 8 + i;
        if (gr >= N_NODES) break;
        float d  = g_dis[gr];
        float d2 = d * d;
        size_t base = (size_t)gr * FEAT + tx * 8;
        #pragma unroll
        for (int j = 0; j < 8; j += 4) {
            float4 v = make_float4(acc[i][j], acc[i][j+1], acc[i][j+2], acc[i][j+3]);
            *(float4*)(g_xw + base + j) = v;
            float4 o;
            o.x = fmaf(v.x, d2, b[tx * 8 + j + 0]);
            o.y = fmaf(v.y, d2, b[tx * 8 + j + 1]);
            o.z = fmaf(v.z, d2, b[tx * 8 + j + 2]);
            o.w = fmaf(v.w, d2, b[tx * 8 + j + 3]);
            *(float4*)(out + base + j) = o;
        }
    }
}

// ---------------------------------------------------------------------------
// Edge scatter: one warp per edge. Gather a full 512B xw row (coalesced
// LDG.128 across the warp), scale by symmetric norm, vectorized RED into out.
// ---------------------------------------------------------------------------
__global__ __launch_bounds__(256) void scatter_kernel(
    const void* __restrict__ ei, float* __restrict__ out)
{
    long long gw = ((long long)blockIdx.x * blockDim.x + threadIdx.x) >> 5;
    int lane = threadIdx.x & 31;
    if (gw >= N_EDGES) return;

    long long r = edge_at(ei, gw);                          // source
    long long c = edge_at(ei, (long long)N_EDGES + gw);     // target
    float nrm = g_dis[r] * g_dis[c];

    float4 v = *((const float4*)(g_xw + r * FEAT) + lane);
    v.x *= nrm; v.y *= nrm; v.z *= nrm; v.w *= nrm;

    float* dst = out + c * FEAT + lane * 4;
    asm volatile("red.global.add.v4.f32 [%0], {%1, %2, %3, %4};"
                 :: "l"(dst), "f"(v.x), "f"(v.y), "f"(v.z), "f"(v.w)
                 : "memory");
}

// ---------------------------------------------------------------------------
extern "C" void kernel_launch(void* const* d_in, const int* in_sizes, int n_in,
                              void* d_out, int out_size)
{
    const float* x  = (const float*)d_in[0];
    const float* W  = (const float*)d_in[1];
    const float* b  = (const float*)d_in[2];
    const void*  ei = d_in[3];
    float* out = (float*)d_out;

    detect_kernel<<<1, 1>>>((const unsigned int*)ei);
    zero_deg_kernel<<<(N_NODES + 255) / 256, 256>>>();
    count_kernel<<<(N_EDGES + 255) / 256, 256>>>(ei);
    rsqrt_kernel<<<(N_NODES + 255) / 256, 256>>>();
    gemm_kernel<<<(N_NODES + 127) / 128, 256>>>(x, W, b, out);

    long long scatter_threads = (long long)N_EDGES * 32;
    int scatter_blocks = (int)((scatter_threads + 255) / 256);
    scatter_kernel<<<scatter_blocks, 256>>>(ei, out);
}

// round 3
// speedup vs baseline: 1.6075x; 1.6075x over previous
#include <cuda_runtime.h>
#include <cstdint>

#define N_NODES 100000
#define N_EDGES 1600000
#define FEAT 128
#define SCAN_BLK 1024
#define N_SBLK ((N_NODES + SCAN_BLK - 1) / SCAN_BLK)   // 98

// Scratch (static device globals — no allocation).
__device__ float g_xw[(size_t)N_NODES * FEAT];   // 51.2 MB
__device__ float g_dis[N_NODES];
__device__ int   g_degi[N_NODES];
__device__ int   g_base[N_NODES];
__device__ int   g_cur[N_NODES];
__device__ int   g_bsum[N_SBLK];
__device__ int   g_src[N_EDGES];                 // CSR: source ids grouped by target
__device__ int   g_is64;

// ---------------------------------------------------------------------------
// Detect int64 vs int32 edge_index (node ids < 100000 => int64 odd words all 0)
// ---------------------------------------------------------------------------
__global__ void detect_kernel(const unsigned int* __restrict__ w) {
    int is64 = 1;
    for (int i = 0; i < 64; i++)
        if (w[2 * i + 1] != 0u) { is64 = 0; break; }
    g_is64 = is64;
}

__device__ __forceinline__ long long edge_at(const void* p, long long i) {
    if (g_is64) return ((const long long*)p)[i];
    return (long long)((const int*)p)[i];
}

// ---------------------------------------------------------------------------
// CSR build: histogram -> exclusive scan -> fill
// ---------------------------------------------------------------------------
__global__ void zero_deg_kernel() {
    int i = blockIdx.x * blockDim.x + threadIdx.x;
    if (i < N_NODES) g_degi[i] = 0;
}

__global__ void hist_kernel(const void* __restrict__ ei) {
    int e = blockIdx.x * blockDim.x + threadIdx.x;
    if (e >= N_EDGES) return;
    int c = (int)edge_at(ei, (long long)N_EDGES + e);   // target
    atomicAdd(&g_degi[c], 1);
}

__global__ void rsqrt_kernel() {
    int i = blockIdx.x * blockDim.x + threadIdx.x;
    if (i < N_NODES) g_dis[i] = rsqrtf((float)g_degi[i] + 1.0f);  // +1 self-loop
}

// Block-level exclusive scan (Hillis-Steele in shared), writes per-block sums.
__global__ __launch_bounds__(SCAN_BLK) void scan1_kernel() {
    __shared__ int sh[SCAN_BLK];
    int i = blockIdx.x * SCAN_BLK + threadIdx.x;
    int v = (i < N_NODES) ? g_degi[i] : 0;
    sh[threadIdx.x] = v;
    __syncthreads();
    #pragma unroll
    for (int off = 1; off < SCAN_BLK; off <<= 1) {
        int t = (threadIdx.x >= off) ? sh[threadIdx.x - off] : 0;
        __syncthreads();
        sh[threadIdx.x] += t;
        __syncthreads();
    }
    if (i < N_NODES) g_base[i] = sh[threadIdx.x] - v;   // exclusive within block
    if (threadIdx.x == SCAN_BLK - 1) g_bsum[blockIdx.x] = sh[SCAN_BLK - 1];
}

__global__ void scan2_kernel() {
    __shared__ int sh[128];
    int t = threadIdx.x;
    sh[t] = (t < N_SBLK) ? g_bsum[t] : 0;
    __syncthreads();
    if (t == 0) {
        int run = 0;
        for (int i = 0; i < N_SBLK; i++) { int v = sh[i]; sh[i] = run; run += v; }
    }
    __syncthreads();
    if (t < N_SBLK) g_bsum[t] = sh[t];
}

__global__ void scan3_kernel() {
    int i = blockIdx.x * blockDim.x + threadIdx.x;
    if (i >= N_NODES) return;
    int base = g_base[i] + g_bsum[i >> 10];
    g_base[i] = base;
    g_cur[i]  = base;
}

__global__ void fill_kernel(const void* __restrict__ ei) {
    int e = blockIdx.x * blockDim.x + threadIdx.x;
    if (e >= N_EDGES) return;
    int r = (int)edge_at(ei, e);                        // source
    int c = (int)edge_at(ei, (long long)N_EDGES + e);   // target
    int pos = atomicAdd(&g_cur[c], 1);
    g_src[pos] = r;
}

// ---------------------------------------------------------------------------
// GEMM: g_xw = x @ W. 128x128 block tile, 256 threads, 8x8 register tile.
// ---------------------------------------------------------------------------
__global__ __launch_bounds__(256) void gemm_kernel(
    const float* __restrict__ x, const float* __restrict__ W)
{
    __shared__ float xs[16][128];   // [k][row] (transposed)
    __shared__ float ws[16][128];   // [k][col]

    const int tid = threadIdx.x;
    const int tx = tid & 15;
    const int ty = tid >> 4;
    const int row0 = blockIdx.x * 128;

    float acc[8][8];
    #pragma unroll
    for (int i = 0; i < 8; i++)
        #pragma unroll
        for (int j = 0; j < 8; j++) acc[i][j] = 0.0f;

    const int lr  = tid >> 2;
    const int lc4 = tid & 3;

    for (int k0 = 0; k0 < FEAT; k0 += 16) {
        #pragma unroll
        for (int p = 0; p < 2; p++) {
            int r  = lr + p * 64;
            int gr = row0 + r;
            float4 v = make_float4(0.f, 0.f, 0.f, 0.f);
            if (gr < N_NODES)
                v = *(const float4*)(x + (size_t)gr * FEAT + k0 + lc4 * 4);
            xs[lc4 * 4 + 0][r] = v.x;
            xs[lc4 * 4 + 1][r] = v.y;
            xs[lc4 * 4 + 2][r] = v.z;
            xs[lc4 * 4 + 3][r] = v.w;
        }
        #pragma unroll
        for (int p = 0; p < 2; p++) {
            int idx = tid + p * 256;
            int kr  = idx >> 5;
            int c4  = idx & 31;
            *(float4*)&ws[kr][c4 * 4] =
                *(const float4*)(W + (size_t)(k0 + kr) * FEAT + c4 * 4);
        }
        __syncthreads();

        #pragma unroll
        for (int kk = 0; kk < 16; kk++) {
            float a[8], w[8];
            #pragma unroll
            for (int i = 0; i < 8; i++) a[i] = xs[kk][ty * 8 + i];
            #pragma unroll
            for (int j = 0; j < 8; j++) w[j] = ws[kk][tx * 8 + j];
            #pragma unroll
            for (int i = 0; i < 8; i++)
                #pragma unroll
                for (int j = 0; j < 8; j++)
                    acc[i][j] = fmaf(a[i], w[j], acc[i][j]);
        }
        __syncthreads();
    }

    #pragma unroll
    for (int i = 0; i < 8; i++) {
        int gr = row0 + ty * 8 + i;
        if (gr >= N_NODES) break;
        size_t base = (size_t)gr * FEAT + tx * 8;
        #pragma unroll
        for (int j = 0; j < 8; j += 4)
            *(float4*)(g_xw + base + j) =
                make_float4(acc[i][j], acc[i][j+1], acc[i][j+2], acc[i][j+3]);
    }
}

// ---------------------------------------------------------------------------
// Gather: one warp per target node. Accumulate in-edge messages in registers,
// add self-loop + bias, single plain 512B store. No atomics.
// ---------------------------------------------------------------------------
__global__ __launch_bounds__(256) void gather_kernel(
    const float* __restrict__ b, float* __restrict__ out)
{
    int node = blockIdx.x * 8 + (threadIdx.x >> 5);
    if (node >= N_NODES) return;
    int lane = threadIdx.x & 31;

    float dc = g_dis[node];
    float d2 = dc * dc;

    float4 acc = ((const float4*)(g_xw + (size_t)node * FEAT))[lane];
    acc.x *= d2; acc.y *= d2; acc.z *= d2; acc.w *= d2;   // self-loop message

    int base = g_base[node];
    int deg  = g_degi[node];

    int i = 0;
    for (; i + 1 < deg; i += 2) {
        int r0 = g_src[base + i];
        int r1 = g_src[base + i + 1];
        float n0 = g_dis[r0] * dc;
        float n1 = g_dis[r1] * dc;
        float4 v0 = ((const float4*)(g_xw + (size_t)r0 * FEAT))[lane];
        float4 v1 = ((const float4*)(g_xw + (size_t)r1 * FEAT))[lane];
        acc.x = fmaf(v0.x, n0, acc.x); acc.y = fmaf(v0.y, n0, acc.y);
        acc.z = fmaf(v0.z, n0, acc.z); acc.w = fmaf(v0.w, n0, acc.w);
        acc.x = fmaf(v1.x, n1, acc.x); acc.y = fmaf(v1.y, n1, acc.y);
        acc.z = fmaf(v1.z, n1, acc.z); acc.w = fmaf(v1.w, n1, acc.w);
    }
    if (i < deg) {
        int r0 = g_src[base + i];
        float n0 = g_dis[r0] * dc;
        float4 v0 = ((const float4*)(g_xw + (size_t)r0 * FEAT))[lane];
        acc.x = fmaf(v0.x, n0, acc.x); acc.y = fmaf(v0.y, n0, acc.y);
        acc.z = fmaf(v0.z, n0, acc.z); acc.w = fmaf(v0.w, n0, acc.w);
    }

    float4 bb = ((const float4*)b)[lane];
    acc.x += bb.x; acc.y += bb.y; acc.z += bb.z; acc.w += bb.w;
    ((float4*)(out + (size_t)node * FEAT))[lane] = acc;
}

// ---------------------------------------------------------------------------
extern "C" void kernel_launch(void* const* d_in, const int* in_sizes, int n_in,
                              void* d_out, int out_size)
{
    const float* x  = (const float*)d_in[0];
    const float* W  = (const float*)d_in[1];
    const float* b  = (const float*)d_in[2];
    const void*  ei = d_in[3];
    float* out = (float*)d_out;

    detect_kernel<<<1, 1>>>((const unsigned int*)ei);
    zero_deg_kernel<<<(N_NODES + 255) / 256, 256>>>();
    hist_kernel<<<(N_EDGES + 255) / 256, 256>>>(ei);
    rsqrt_kernel<<<(N_NODES + 255) / 256, 256>>>();
    scan1_kernel<<<N_SBLK, SCAN_BLK>>>();
    scan2_kernel<<<1, 128>>>();
    scan3_kernel<<<(N_NODES + 255) / 256, 256>>>();
    fill_kernel<<<(N_EDGES + 255) / 256, 256>>>(ei);
    gemm_kernel<<<(N_NODES + 127) / 128, 256>>>(x, W);
    gather_kernel<<<(N_NODES + 7) / 8, 256>>>(b, out);
}

// round 4
// speedup vs baseline: 1.7210x; 1.0706x over previous
#include <cuda_runtime.h>
#include <cstdint>

#define N_NODES 100000
#define N_EDGES 1600000
#define FEAT 128
#define SCAN_BLK 1024
#define N_SBLK ((N_NODES + SCAN_BLK - 1) / SCAN_BLK)   // 98

// Scratch (static device globals — no allocation).
__device__ float g_xw[(size_t)N_NODES * FEAT];   // 51.2 MB
__device__ float g_dis[N_NODES];
__device__ int   g_degi[N_NODES];
__device__ int   g_base[N_NODES];
__device__ int   g_cur[N_NODES];
__device__ int   g_bsum[N_SBLK];
__device__ int   g_src[N_EDGES];                 // CSR: source ids grouped by target
__device__ int   g_is64;

// ---------------------------------------------------------------------------
__device__ __forceinline__ long long edge_at(const void* p, long long i) {
    if (g_is64) return ((const long long*)p)[i];
    return (long long)((const int*)p)[i];
}

// init: zero degree histogram; thread 0 also detects int64 vs int32 edge_index
// (node ids < 100000 => for int64 every odd 32-bit word is 0).
__global__ void init_kernel(const unsigned int* __restrict__ w) {
    int i = blockIdx.x * blockDim.x + threadIdx.x;
    if (i < N_NODES) g_degi[i] = 0;
    if (blockIdx.x == 0 && threadIdx.x == 0) {
        int is64 = 1;
        for (int k = 0; k < 64; k++)
            if (w[2 * k + 1] != 0u) { is64 = 0; break; }
        g_is64 = is64;
    }
}

__global__ void hist_kernel(const void* __restrict__ ei) {
    int e = blockIdx.x * blockDim.x + threadIdx.x;
    if (e >= N_EDGES) return;
    int c = (int)edge_at(ei, (long long)N_EDGES + e);   // target
    atomicAdd(&g_degi[c], 1);
}

// Block-level exclusive scan; also computes dis = rsqrt(deg+1).
__global__ __launch_bounds__(SCAN_BLK) void scan1_kernel() {
    __shared__ int sh[SCAN_BLK];
    int i = blockIdx.x * SCAN_BLK + threadIdx.x;
    int v = (i < N_NODES) ? g_degi[i] : 0;
    if (i < N_NODES) g_dis[i] = rsqrtf((float)v + 1.0f);
    sh[threadIdx.x] = v;
    __syncthreads();
    #pragma unroll
    for (int off = 1; off < SCAN_BLK; off <<= 1) {
        int t = (threadIdx.x >= off) ? sh[threadIdx.x - off] : 0;
        __syncthreads();
        sh[threadIdx.x] += t;
        __syncthreads();
    }
    if (i < N_NODES) g_base[i] = sh[threadIdx.x] - v;   // exclusive within block
    if (threadIdx.x == SCAN_BLK - 1) g_bsum[blockIdx.x] = sh[SCAN_BLK - 1];
}

__global__ void scan2_kernel() {
    __shared__ int sh[128];
    int t = threadIdx.x;
    sh[t] = (t < N_SBLK) ? g_bsum[t] : 0;
    __syncthreads();
    if (t == 0) {
        int run = 0;
        for (int i = 0; i < N_SBLK; i++) { int v = sh[i]; sh[i] = run; run += v; }
    }
    __syncthreads();
    if (t < N_SBLK) g_bsum[t] = sh[t];
}

__global__ void scan3_kernel() {
    int i = blockIdx.x * blockDim.x + threadIdx.x;
    if (i >= N_NODES) return;
    int base = g_base[i] + g_bsum[i >> 10];
    g_base[i] = base;
    g_cur[i]  = base;
}

__global__ void fill_kernel(const void* __restrict__ ei) {
    int e = blockIdx.x * blockDim.x + threadIdx.x;
    if (e >= N_EDGES) return;
    int r = (int)edge_at(ei, e);                        // source
    int c = (int)edge_at(ei, (long long)N_EDGES + e);   // target
    int pos = atomicAdd(&g_cur[c], 1);
    g_src[pos] = r;
}

// ---------------------------------------------------------------------------
// TF32 tensor-core GEMM with 3-term split precision:
//   x = x_hi + x_lo (tf32), W = W_hi + W_lo
//   xw ~= x_lo*W_hi + x_hi*W_lo + x_hi*W_hi   (fp32 accum, ~1e-6 rel err)
// 128x128 block tile, 256 threads = 8 warps (4 M x 2 N), each warp 32x64,
// mma.sync.m16n8k8, K chunked by 32 into SMEM.
// ---------------------------------------------------------------------------
#define XS 40    // padded row stride (floats) for x tiles: bank-conflict-free frags
#define WS 136   // padded row stride for W tiles
#define GEMM_SMEM_BYTES ((128 * XS * 2 + 32 * WS * 2) * 4)   // 75776

__device__ __forceinline__ uint32_t f2tf32(float f) {
    uint32_t r;
    asm("cvt.rna.tf32.f32 %0, %1;" : "=r"(r) : "f"(f));
    return r;
}

__device__ __forceinline__ void mma_tf32(float c[4], const uint32_t a[4], const uint32_t b[2]) {
    asm volatile(
        "mma.sync.aligned.m16n8k8.row.col.f32.tf32.tf32.f32 "
        "{%0,%1,%2,%3}, {%4,%5,%6,%7}, {%8,%9}, {%0,%1,%2,%3};"
        : "+f"(c[0]), "+f"(c[1]), "+f"(c[2]), "+f"(c[3])
        : "r"(a[0]), "r"(a[1]), "r"(a[2]), "r"(a[3]), "r"(b[0]), "r"(b[1]));
}

__global__ __launch_bounds__(256) void gemm_kernel(
    const float* __restrict__ x, const float* __restrict__ W)
{
    extern __shared__ uint32_t smem[];
    uint32_t* xs_hi = smem;
    uint32_t* xs_lo = xs_hi + 128 * XS;
    uint32_t* ws_hi = xs_lo + 128 * XS;
    uint32_t* ws_lo = ws_hi + 32 * WS;

    const int tid  = threadIdx.x;
    const int lane = tid & 31;
    const int w    = tid >> 5;      // warp 0..7
    const int wm   = w & 3;         // M warp: rows 32*wm
    const int wn   = w >> 2;        // N warp: cols 64*wn
    const int grp  = lane >> 2;     // 0..7
    const int qid  = lane & 3;      // 0..3
    const int row0 = blockIdx.x * 128;

    float acc[2][8][4];
    #pragma unroll
    for (int mt = 0; mt < 2; mt++)
        #pragma unroll
        for (int nt = 0; nt < 8; nt++)
            #pragma unroll
            for (int q = 0; q < 4; q++) acc[mt][nt][q] = 0.0f;

    for (int kc = 0; kc < FEAT; kc += 32) {
        // Load + split x tile: 128 rows x 32 k
        #pragma unroll
        for (int i = 0; i < 4; i++) {
            int idx = tid + i * 256;         // 0..1023 float4 slots
            int r   = idx >> 3;              // 0..127
            int c4  = idx & 7;               // 0..7
            int gr  = row0 + r;
            float4 v = make_float4(0.f, 0.f, 0.f, 0.f);
            if (gr < N_NODES)
                v = *(const float4*)(x + (size_t)gr * FEAT + kc + c4 * 4);
            const float vv[4] = {v.x, v.y, v.z, v.w};
            #pragma unroll
            for (int j = 0; j < 4; j++) {
                uint32_t hi = f2tf32(vv[j]);
                float hif = __uint_as_float(hi);
                uint32_t lo = f2tf32(vv[j] - hif);
                xs_hi[r * XS + c4 * 4 + j] = hi;
                xs_lo[r * XS + c4 * 4 + j] = lo;
            }
        }
        // Load + split W tile: 32 k x 128 cols
        #pragma unroll
        for (int i = 0; i < 4; i++) {
            int idx = tid + i * 256;
            int kr  = idx >> 5;              // 0..31
            int c4  = idx & 31;              // 0..31
            float4 v = *(const float4*)(W + (size_t)(kc + kr) * FEAT + c4 * 4);
            const float vv[4] = {v.x, v.y, v.z, v.w};
            #pragma unroll
            for (int j = 0; j < 4; j++) {
                uint32_t hi = f2tf32(vv[j]);
                float hif = __uint_as_float(hi);
                uint32_t lo = f2tf32(vv[j] - hif);
                ws_hi[kr * WS + c4 * 4 + j] = hi;
                ws_lo[kr * WS + c4 * 4 + j] = lo;
            }
        }
        __syncthreads();

        #pragma unroll
        for (int ks = 0; ks < 32; ks += 8) {
            uint32_t a_hi[2][4], a_lo[2][4];
            #pragma unroll
            for (int mt = 0; mt < 2; mt++) {
                int r0 = 32 * wm + 16 * mt;
                a_hi[mt][0] = xs_hi[(r0 + grp) * XS + ks + qid];
                a_hi[mt][1] = xs_hi[(r0 + grp + 8) * XS + ks + qid];
                a_hi[mt][2] = xs_hi[(r0 + grp) * XS + ks + qid + 4];
                a_hi[mt][3] = xs_hi[(r0 + grp + 8) * XS + ks + qid + 4];
                a_lo[mt][0] = xs_lo[(r0 + grp) * XS + ks + qid];
                a_lo[mt][1] = xs_lo[(r0 + grp + 8) * XS + ks + qid];
                a_lo[mt][2] = xs_lo[(r0 + grp) * XS + ks + qid + 4];
                a_lo[mt][3] = xs_lo[(r0 + grp + 8) * XS + ks + qid + 4];
            }
            #pragma unroll
            for (int nt = 0; nt < 8; nt++) {
                int n0 = 64 * wn + 8 * nt;
                uint32_t b_hi[2], b_lo[2];
                b_hi[0] = ws_hi[(ks + qid) * WS + n0 + grp];
                b_hi[1] = ws_hi[(ks + qid + 4) * WS + n0 + grp];
                b_lo[0] = ws_lo[(ks + qid) * WS + n0 + grp];
                b_lo[1] = ws_lo[(ks + qid + 4) * WS + n0 + grp];
                #pragma unroll
                for (int mt = 0; mt < 2; mt++) {
                    mma_tf32(acc[mt][nt], a_lo[mt], b_hi);
                    mma_tf32(acc[mt][nt], a_hi[mt], b_lo);
                    mma_tf32(acc[mt][nt], a_hi[mt], b_hi);
                }
            }
        }
        __syncthreads();
    }

    // Epilogue: write g_xw
    #pragma unroll
    for (int mt = 0; mt < 2; mt++) {
        int r0 = row0 + 32 * wm + 16 * mt + grp;
        #pragma unroll
        for (int nt = 0; nt < 8; nt++) {
            int cb = 64 * wn + 8 * nt + 2 * qid;
            if (r0 < N_NODES)
                *(float2*)(g_xw + (size_t)r0 * FEAT + cb) =
                    make_float2(acc[mt][nt][0], acc[mt][nt][1]);
            if (r0 + 8 < N_NODES)
                *(float2*)(g_xw + (size_t)(r0 + 8) * FEAT + cb) =
                    make_float2(acc[mt][nt][2], acc[mt][nt][3]);
        }
    }
}

// ---------------------------------------------------------------------------
// Gather: one warp per target node; register accumulation, no atomics.
// ---------------------------------------------------------------------------
__global__ __launch_bounds__(256) void gather_kernel(
    const float* __restrict__ b, float* __restrict__ out)
{
    int node = blockIdx.x * 8 + (threadIdx.x >> 5);
    if (node >= N_NODES) return;
    int lane = threadIdx.x & 31;

    float dc = g_dis[node];
    float d2 = dc * dc;

    float4 acc = ((const float4*)(g_xw + (size_t)node * FEAT))[lane];
    acc.x *= d2; acc.y *= d2; acc.z *= d2; acc.w *= d2;   // self-loop message

    int base = g_base[node];
    int deg  = g_degi[node];

    int i = 0;
    for (; i + 1 < deg; i += 2) {
        int r0 = g_src[base + i];
        int r1 = g_src[base + i + 1];
        float n0 = g_dis[r0] * dc;
        float n1 = g_dis[r1] * dc;
        float4 v0 = ((const float4*)(g_xw + (size_t)r0 * FEAT))[lane];
        float4 v1 = ((const float4*)(g_xw + (size_t)r1 * FEAT))[lane];
        acc.x = fmaf(v0.x, n0, acc.x); acc.y = fmaf(v0.y, n0, acc.y);
        acc.z = fmaf(v0.z, n0, acc.z); acc.w = fmaf(v0.w, n0, acc.w);
        acc.x = fmaf(v1.x, n1, acc.x); acc.y = fmaf(v1.y, n1, acc.y);
        acc.z = fmaf(v1.z, n1, acc.z); acc.w = fmaf(v1.w, n1, acc.w);
    }
    if (i < deg) {
        int r0 = g_src[base + i];
        float n0 = g_dis[r0] * dc;
        float4 v0 = ((const float4*)(g_xw + (size_t)r0 * FEAT))[lane];
        acc.x = fmaf(v0.x, n0, acc.x); acc.y = fmaf(v0.y, n0, acc.y);
        acc.z = fmaf(v0.z, n0, acc.z); acc.w = fmaf(v0.w, n0, acc.w);
    }

    float4 bb = ((const float4*)b)[lane];
    acc.x += bb.x; acc.y += bb.y; acc.z += bb.z; acc.w += bb.w;
    ((float4*)(out + (size_t)node * FEAT))[lane] = acc;
}

// ---------------------------------------------------------------------------
extern "C" void kernel_launch(void* const* d_in, const int* in_sizes, int n_in,
                              void* d_out, int out_size)
{
    const float* x  = (const float*)d_in[0];
    const float* W  = (const float*)d_in[1];
    const float* b  = (const float*)d_in[2];
    const void*  ei = d_in[3];
    float* out = (float*)d_out;

    cudaFuncSetAttribute(gemm_kernel,
                         cudaFuncAttributeMaxDynamicSharedMemorySize,
                         GEMM_SMEM_BYTES);

    init_kernel<<<(N_NODES + 255) / 256, 256>>>((const unsigned int*)ei);
    hist_kernel<<<(N_EDGES + 255) / 256, 256>>>(ei);
    scan1_kernel<<<N_SBLK, SCAN_BLK>>>();
    scan2_kernel<<<1, 128>>>();
    scan3_kernel<<<(N_NODES + 255) / 256, 256>>>();
    fill_kernel<<<(N_EDGES + 255) / 256, 256>>>(ei);
    gemm_kernel<<<(N_NODES + 127) / 128, 256, GEMM_SMEM_BYTES>>>(x, W);
    gather_kernel<<<(N_NODES + 7) / 8, 256>>>(b, out);
}

// round 6
// speedup vs baseline: 2.0464x; 1.1891x over previous
#include <cuda_runtime.h>
#include <cuda_bf16.h>
#include <cuda_fp16.h>
#include <cstdint>

#define N_NODES 100000
#define N_EDGES 1600000
#define FEAT 128
#define SCAN_BLK 1024
#define N_SBLK ((N_NODES + SCAN_BLK - 1) / SCAN_BLK)   // 98

// Scratch (static device globals — no allocation).
__device__ __half g_xw[(size_t)N_NODES * FEAT];  // 25.6 MB (fp16 xw)
__device__ float g_dis[N_NODES];
__device__ int   g_degi[N_NODES];
__device__ int   g_base[N_NODES];
__device__ int   g_cur[N_NODES];
__device__ int   g_bsum[N_SBLK];
__device__ int   g_src[N_EDGES];
__device__ int   g_is64;
// W transposed to [n][k], split to bf16 hi/lo, k-pairs packed in uint32.
__device__ uint32_t g_Whi[128 * 64];
__device__ uint32_t g_Wlo[128 * 64];

// ---------------------------------------------------------------------------
__device__ __forceinline__ long long edge_at(const void* p, long long i) {
    if (g_is64) return ((const long long*)p)[i];
    return (long long)((const int*)p)[i];
}

__global__ void init_kernel(const unsigned int* __restrict__ w) {
    int i = blockIdx.x * blockDim.x + threadIdx.x;
    if (i < N_NODES) g_degi[i] = 0;
    if (blockIdx.x == 0 && threadIdx.x == 0) {
        int is64 = 1;
        for (int k = 0; k < 64; k++)
            if (w[2 * k + 1] != 0u) { is64 = 0; break; }
        g_is64 = is64;
    }
}

__global__ void hist_kernel(const void* __restrict__ ei) {
    int e = blockIdx.x * blockDim.x + threadIdx.x;
    if (e >= N_EDGES) return;
    int c = (int)edge_at(ei, (long long)N_EDGES + e);
    atomicAdd(&g_degi[c], 1);
}

// Block-level exclusive scan; also computes dis = rsqrt(deg+1).
__global__ __launch_bounds__(SCAN_BLK) void scan1_kernel() {
    __shared__ int sh[SCAN_BLK];
    int i = blockIdx.x * SCAN_BLK + threadIdx.x;
    int v = (i < N_NODES) ? g_degi[i] : 0;
    if (i < N_NODES) g_dis[i] = rsqrtf((float)v + 1.0f);
    sh[threadIdx.x] = v;
    __syncthreads();
    #pragma unroll
    for (int off = 1; off < SCAN_BLK; off <<= 1) {
        int t = (threadIdx.x >= off) ? sh[threadIdx.x - off] : 0;
        __syncthreads();
        sh[threadIdx.x] += t;
        __syncthreads();
    }
    if (i < N_NODES) g_base[i] = sh[threadIdx.x] - v;
    if (threadIdx.x == SCAN_BLK - 1) g_bsum[blockIdx.x] = sh[SCAN_BLK - 1];
}

// Merged scan2+scan3: warp 0 computes the bsum prefix for this block's chunk.
__global__ void scan23_kernel() {
    __shared__ int s_pref;
    int i = blockIdx.x * blockDim.x + threadIdx.x;
    int sb = (blockIdx.x * blockDim.x) >> 10;
    if (threadIdx.x < 32) {
        int acc = 0;
        for (int j = threadIdx.x; j < sb; j += 32) acc += g_bsum[j];
        #pragma unroll
        for (int off = 16; off > 0; off >>= 1)
            acc += __shfl_xor_sync(0xffffffffu, acc, off);
        if (threadIdx.x == 0) s_pref = acc;
    }
    __syncthreads();
    if (i >= N_NODES) return;
    int base = g_base[i] + s_pref;
    g_base[i] = base;
    g_cur[i]  = base;
}

__global__ void fill_kernel(const void* __restrict__ ei) {
    int e = blockIdx.x * blockDim.x + threadIdx.x;
    if (e >= N_EDGES) return;
    int r = (int)edge_at(ei, e);
    int c = (int)edge_at(ei, (long long)N_EDGES + e);
    int pos = atomicAdd(&g_cur[c], 1);
    g_src[pos] = r;
}

// ---------------------------------------------------------------------------
// W prep: transpose W[k][n] -> [n][k], split each element to bf16 hi/lo,
// pack k-pairs into uint32 (low half = even k).
// ---------------------------------------------------------------------------
__global__ void wprep_kernel(const float* __restrict__ W) {
    int idx = blockIdx.x * blockDim.x + threadIdx.x;   // 0..8191
    if (idx >= 8192) return;
    int n  = idx >> 6;          // 0..127
    int kp = idx & 63;          // k-pair 0..63
    float v0 = W[(size_t)(2 * kp) * FEAT + n];
    float v1 = W[(size_t)(2 * kp + 1) * FEAT + n];
    __nv_bfloat16 h0 = __float2bfloat16(v0);
    __nv_bfloat16 h1 = __float2bfloat16(v1);
    __nv_bfloat16 l0 = __float2bfloat16(v0 - __bfloat162float(h0));
    __nv_bfloat16 l1 = __float2bfloat16(v1 - __bfloat162float(h1));
    g_Whi[n * 64 + kp] = (uint32_t)__bfloat16_as_ushort(h0) |
                         ((uint32_t)__bfloat16_as_ushort(h1) << 16);
    g_Wlo[n * 64 + kp] = (uint32_t)__bfloat16_as_ushort(l0) |
                         ((uint32_t)__bfloat16_as_ushort(l1) << 16);
}

// ---------------------------------------------------------------------------
// BF16 tensor-core GEMM (mma.sync.m16n8k16), 3-term split precision:
//   xw ~= x_hi*W_hi + x_lo*W_hi + x_hi*W_lo   (fp32 accum)
// 128x128 block tile, 256 threads = 8 warps (4M x 2N), warp tile 32x64.
// A chunked by K=32 into SMEM; full split-W resident in SMEM.
// Output stored as fp16.
// ---------------------------------------------------------------------------
#define XSP 36   // x tile row stride in uint32 (16 pairs + pad; 4*grp+qid banks)
#define WSP 68   // W row stride in uint32 (64 pairs + pad; conflict-free)
#define GEMM_SMEM ((2 * 128 * XSP + 2 * 128 * WSP) * 4)   // 106496 bytes

__device__ __forceinline__ void mma_bf16(float c[4], const uint32_t a[4],
                                         const uint32_t b[2]) {
    asm volatile(
        "mma.sync.aligned.m16n8k16.row.col.f32.bf16.bf16.f32 "
        "{%0,%1,%2,%3}, {%4,%5,%6,%7}, {%8,%9}, {%0,%1,%2,%3};"
        : "+f"(c[0]), "+f"(c[1]), "+f"(c[2]), "+f"(c[3])
        : "r"(a[0]), "r"(a[1]), "r"(a[2]), "r"(a[3]), "r"(b[0]), "r"(b[1]));
}

__global__ __launch_bounds__(256) void gemm_kernel(const float* __restrict__ x)
{
    extern __shared__ uint32_t smem[];
    uint32_t* xs_hi = smem;                    // [128][XSP]
    uint32_t* xs_lo = xs_hi + 128 * XSP;
    uint32_t* ws_hi = xs_lo + 128 * XSP;       // [128][WSP]
    uint32_t* ws_lo = ws_hi + 128 * WSP;

    const int tid  = threadIdx.x;
    const int lane = tid & 31;
    const int w    = tid >> 5;
    const int wm   = w & 3;         // rows 32*wm
    const int wn   = w >> 2;        // cols 64*wn
    const int grp  = lane >> 2;
    const int qid  = lane & 3;
    const int row0 = blockIdx.x * 128;

    // Copy precomputed W images (L2-resident) into padded SMEM.
    {
        int r = tid >> 1;           // 0..127
        int h = tid & 1;            // half-row
        const uint4* sh = (const uint4*)&g_Whi[r * 64 + h * 32];
        const uint4* sl = (const uint4*)&g_Wlo[r * 64 + h * 32];
        uint4* dh = (uint4*)&ws_hi[r * WSP + h * 32];
        uint4* dl = (uint4*)&ws_lo[r * WSP + h * 32];
        #pragma unroll
        for (int i = 0; i < 8; i++) { dh[i] = sh[i]; dl[i] = sl[i]; }
    }

    float acc[2][8][4];
    #pragma unroll
    for (int mt = 0; mt < 2; mt++)
        #pragma unroll
        for (int nt = 0; nt < 8; nt++)
            #pragma unroll
            for (int q = 0; q < 4; q++) acc[mt][nt][q] = 0.0f;

    for (int kc = 0; kc < 4; kc++) {            // K chunk = 32
        // Load + split x chunk: 128 rows x 32 k
        #pragma unroll
        for (int i = 0; i < 4; i++) {
            int idx = tid + i * 256;            // float4 slot
            int r   = idx >> 3;
            int c4  = idx & 7;
            int gr  = row0 + r;
            float4 v = make_float4(0.f, 0.f, 0.f, 0.f);
            if (gr < N_NODES)
                v = *(const float4*)(x + (size_t)gr * FEAT + kc * 32 + c4 * 4);
            const float vv[4] = {v.x, v.y, v.z, v.w};
            #pragma unroll
            for (int j = 0; j < 2; j++) {
                float a0 = vv[2 * j], a1 = vv[2 * j + 1];
                __nv_bfloat16 h0 = __float2bfloat16(a0);
                __nv_bfloat16 h1 = __float2bfloat16(a1);
                __nv_bfloat16 l0 = __float2bfloat16(a0 - __bfloat162float(h0));
                __nv_bfloat16 l1 = __float2bfloat16(a1 - __bfloat162float(h1));
                xs_hi[r * XSP + c4 * 2 + j] =
                    (uint32_t)__bfloat16_as_ushort(h0) |
                    ((uint32_t)__bfloat16_as_ushort(h1) << 16);
                xs_lo[r * XSP + c4 * 2 + j] =
                    (uint32_t)__bfloat16_as_ushort(l0) |
                    ((uint32_t)__bfloat16_as_ushort(l1) << 16);
            }
        }
        __syncthreads();

        #pragma unroll
        for (int ks = 0; ks < 2; ks++) {        // two K=16 steps per chunk
            int xp = ks * 8;                    // x pair offset in chunk
            int wp = kc * 16 + ks * 8;          // W pair offset global
            uint32_t a_hi[2][4], a_lo[2][4];
            #pragma unroll
            for (int mt = 0; mt < 2; mt++) {
                int r0 = 32 * wm + 16 * mt;
                int i0 = (r0 + grp) * XSP + xp + qid;
                int i1 = (r0 + grp + 8) * XSP + xp + qid;
                a_hi[mt][0] = xs_hi[i0];
                a_hi[mt][1] = xs_hi[i1];
                a_hi[mt][2] = xs_hi[i0 + 4];
                a_hi[mt][3] = xs_hi[i1 + 4];
                a_lo[mt][0] = xs_lo[i0];
                a_lo[mt][1] = xs_lo[i1];
                a_lo[mt][2] = xs_lo[i0 + 4];
                a_lo[mt][3] = xs_lo[i1 + 4];
            }
            #pragma unroll
            for (int nt = 0; nt < 8; nt++) {
                int nb = (64 * wn + 8 * nt + grp) * WSP + wp + qid;
                uint32_t b_hi[2], b_lo[2];
                b_hi[0] = ws_hi[nb];
                b_hi[1] = ws_hi[nb + 4];
                b_lo[0] = ws_lo[nb];
                b_lo[1] = ws_lo[nb + 4];
                #pragma unroll
                for (int mt = 0; mt < 2; mt++) {
                    mma_bf16(acc[mt][nt], a_lo[mt], b_hi);
                    mma_bf16(acc[mt][nt], a_hi[mt], b_lo);
                    mma_bf16(acc[mt][nt], a_hi[mt], b_hi);
                }
            }
        }
        __syncthreads();
    }

    // Epilogue: write fp16 xw (half2 stores).
    #pragma unroll
    for (int mt = 0; mt < 2; mt++) {
        int r0 = row0 + 32 * wm + 16 * mt + grp;
        #pragma unroll
        for (int nt = 0; nt < 8; nt++) {
            int cb = 64 * wn + 8 * nt + 2 * qid;
            if (r0 < N_NODES)
                *(__half2*)(g_xw + (size_t)r0 * FEAT + cb) =
                    __floats2half2_rn(acc[mt][nt][0], acc[mt][nt][1]);
            if (r0 + 8 < N_NODES)
                *(__half2*)(g_xw + (size_t)(r0 + 8) * FEAT + cb) =
                    __floats2half2_rn(acc[mt][nt][2], acc[mt][nt][3]);
        }
    }
}

// ---------------------------------------------------------------------------
// Gather: one warp per target node; fp16 row reads (8B/lane), fp32 accum.
// ---------------------------------------------------------------------------
__device__ __forceinline__ float4 load_row4(long long node, int lane) {
    uint2 u = *((const uint2*)(g_xw + (size_t)node * FEAT) + lane);
    __half2 p0 = *reinterpret_cast<__half2*>(&u.x);
    __half2 p1 = *reinterpret_cast<__half2*>(&u.y);
    float2 f0 = __half22float2(p0);
    float2 f1 = __half22float2(p1);
    return make_float4(f0.x, f0.y, f1.x, f1.y);
}

__global__ __launch_bounds__(256) void gather_kernel(
    const float* __restrict__ b, float* __restrict__ out)
{
    int node = blockIdx.x * 8 + (threadIdx.x >> 5);
    if (node >= N_NODES) return;
    int lane = threadIdx.x & 31;

    float dc = g_dis[node];
    float d2 = dc * dc;

    float4 acc = load_row4(node, lane);
    acc.x *= d2; acc.y *= d2; acc.z *= d2; acc.w *= d2;   // self-loop

    int base = g_base[node];
    int deg  = g_degi[node];

    int i = 0;
    for (; i + 1 < deg; i += 2) {
        int r0 = g_src[base + i];
        int r1 = g_src[base + i + 1];
        float n0 = g_dis[r0] * dc;
        float n1 = g_dis[r1] * dc;
        float4 v0 = load_row4(r0, lane);
        float4 v1 = load_row4(r1, lane);
        acc.x = fmaf(v0.x, n0, acc.x); acc.y = fmaf(v0.y, n0, acc.y);
        acc.z = fmaf(v0.z, n0, acc.z); acc.w = fmaf(v0.w, n0, acc.w);
        acc.x = fmaf(v1.x, n1, acc.x); acc.y = fmaf(v1.y, n1, acc.y);
        acc.z = fmaf(v1.z, n1, acc.z); acc.w = fmaf(v1.w, n1, acc.w);
    }
    if (i < deg) {
        int r0 = g_src[base + i];
        float n0 = g_dis[r0] * dc;
        float4 v0 = load_row4(r0, lane);
        acc.x = fmaf(v0.x, n0, acc.x); acc.y = fmaf(v0.y, n0, acc.y);
        acc.z = fmaf(v0.z, n0, acc.z); acc.w = fmaf(v0.w, n0, acc.w);
    }

    float4 bb = ((const float4*)b)[lane];
    acc.x += bb.x; acc.y += bb.y; acc.z += bb.z; acc.w += bb.w;
    ((float4*)(out + (size_t)node * FEAT))[lane] = acc;
}

// ---------------------------------------------------------------------------
extern "C" void kernel_launch(void* const* d_in, const int* in_sizes, int n_in,
                              void* d_out, int out_size)
{
    const float* x  = (const float*)d_in[0];
    const float* W  = (const float*)d_in[1];
    const float* b  = (const float*)d_in[2];
    const void*  ei = d_in[3];
    float* out = (float*)d_out;

    cudaFuncSetAttribute(gemm_kernel,
                         cudaFuncAttributeMaxDynamicSharedMemorySize, GEMM_SMEM);

    init_kernel<<<(N_NODES + 255) / 256, 256>>>((const unsigned int*)ei);
    hist_kernel<<<(N_EDGES + 255) / 256, 256>>>(ei);
    scan1_kernel<<<N_SBLK, SCAN_BLK>>>();
    scan23_kernel<<<(N_NODES + 255) / 256, 256>>>();
    wprep_kernel<<<32, 256>>>(W);
    fill_kernel<<<(N_EDGES + 255) / 256, 256>>>(ei);
    gemm_kernel<<<(N_NODES + 127) / 128, 256, GEMM_SMEM>>>(x);
    gather_kernel<<<(N_NODES + 7) / 8, 256>>>(b, out);
}

// round 7
// speedup vs baseline: 2.0771x; 1.0150x over previous
#include <cuda_runtime.h>
#include <cuda_bf16.h>
#include <cuda_fp16.h>
#include <cstdint>

#define N_NODES 100000
#define N_EDGES 1600000
#define FEAT 128
#define SCAN_BLK 1024
#define N_SBLK ((N_NODES + SCAN_BLK - 1) / SCAN_BLK)   // 98

#define G_GEMM ((N_NODES + 127) / 128)                 // 782 gemm tile blocks
#define G_FILL 1266                                    // fill blocks in fused grid

// Scratch (static device globals — no allocation).
__device__ __half g_xw[(size_t)N_NODES * FEAT];  // 25.6 MB (fp16 xw)
__device__ float g_dis[N_NODES];
__device__ int   g_degi[N_NODES];
__device__ int   g_base[N_NODES];
__device__ int   g_cur[N_NODES];
__device__ int   g_bsum[N_SBLK];
__device__ int   g_src[N_EDGES];
__device__ int   g_is64;
// W transposed to [n][k], split to bf16 hi/lo, k-pairs packed in uint32.
__device__ uint32_t g_Whi[128 * 64];
__device__ uint32_t g_Wlo[128 * 64];

// ---------------------------------------------------------------------------
__device__ __forceinline__ long long edge_at(const void* p, long long i) {
    if (g_is64) return ((const long long*)p)[i];
    return (long long)((const int*)p)[i];
}

// Fused: blocks [0,391) zero degree histogram (+detect int64 in block 0);
//        blocks [391,423) transpose/split W into bf16 hi/lo packed images.
__global__ void init_wprep_kernel(const unsigned int* __restrict__ w,
                                  const float* __restrict__ W) {
    if (blockIdx.x < 391) {
        int i = blockIdx.x * blockDim.x + threadIdx.x;
        if (i < N_NODES) g_degi[i] = 0;
        if (blockIdx.x == 0 && threadIdx.x == 0) {
            int is64 = 1;
            for (int k = 0; k < 64; k++)
                if (w[2 * k + 1] != 0u) { is64 = 0; break; }
            g_is64 = is64;
        }
    } else {
        int idx = (blockIdx.x - 391) * blockDim.x + threadIdx.x;  // 0..8191
        if (idx >= 8192) return;
        int n  = idx >> 6;
        int kp = idx & 63;
        float v0 = W[(size_t)(2 * kp) * FEAT + n];
        float v1 = W[(size_t)(2 * kp + 1) * FEAT + n];
        __nv_bfloat16 h0 = __float2bfloat16(v0);
        __nv_bfloat16 h1 = __float2bfloat16(v1);
        __nv_bfloat16 l0 = __float2bfloat16(v0 - __bfloat162float(h0));
        __nv_bfloat16 l1 = __float2bfloat16(v1 - __bfloat162float(h1));
        g_Whi[n * 64 + kp] = (uint32_t)__bfloat16_as_ushort(h0) |
                             ((uint32_t)__bfloat16_as_ushort(h1) << 16);
        g_Wlo[n * 64 + kp] = (uint32_t)__bfloat16_as_ushort(l0) |
                             ((uint32_t)__bfloat16_as_ushort(l1) << 16);
    }
}

__global__ void hist_kernel(const void* __restrict__ ei) {
    int e = blockIdx.x * blockDim.x + threadIdx.x;
    if (e >= N_EDGES) return;
    int c = (int)edge_at(ei, (long long)N_EDGES + e);
    atomicAdd(&g_degi[c], 1);
}

// Block-level exclusive scan; also computes dis = rsqrt(deg+1).
__global__ __launch_bounds__(SCAN_BLK) void scan1_kernel() {
    __shared__ int sh[SCAN_BLK];
    int i = blockIdx.x * SCAN_BLK + threadIdx.x;
    int v = (i < N_NODES) ? g_degi[i] : 0;
    if (i < N_NODES) g_dis[i] = rsqrtf((float)v + 1.0f);
    sh[threadIdx.x] = v;
    __syncthreads();
    #pragma unroll
    for (int off = 1; off < SCAN_BLK; off <<= 1) {
        int t = (threadIdx.x >= off) ? sh[threadIdx.x - off] : 0;
        __syncthreads();
        sh[threadIdx.x] += t;
        __syncthreads();
    }
    if (i < N_NODES) g_base[i] = sh[threadIdx.x] - v;
    if (threadIdx.x == SCAN_BLK - 1) g_bsum[blockIdx.x] = sh[SCAN_BLK - 1];
}

// Merged scan2+scan3: warp 0 computes the bsum prefix for this block's chunk.
__global__ void scan23_kernel() {
    __shared__ int s_pref;
    int i = blockIdx.x * blockDim.x + threadIdx.x;
    int sb = (blockIdx.x * blockDim.x) >> 10;
    if (threadIdx.x < 32) {
        int acc = 0;
        for (int j = threadIdx.x; j < sb; j += 32) acc += g_bsum[j];
        #pragma unroll
        for (int off = 16; off > 0; off >>= 1)
            acc += __shfl_xor_sync(0xffffffffu, acc, off);
        if (threadIdx.x == 0) s_pref = acc;
    }
    __syncthreads();
    if (i >= N_NODES) return;
    int base = g_base[i] + s_pref;
    g_base[i] = base;
    g_cur[i]  = base;
}

// ---------------------------------------------------------------------------
// Fused GEMM + fill. Blocks [0, G_GEMM) compute 128-row GEMM tiles (bf16
// 3-term split, mma.sync.m16n8k16, fp16 output). Blocks [G_GEMM, G_GEMM+G_FILL)
// grid-stride the CSR fill (independent of GEMM; both follow scan23/wprep).
// ---------------------------------------------------------------------------
#define XSP 36   // x tile row stride in uint32
#define WSP 68   // W row stride in uint32
#define GEMM_SMEM ((2 * 128 * XSP + 2 * 128 * WSP) * 4)   // 106496 bytes

__device__ __forceinline__ void mma_bf16(float c[4], const uint32_t a[4],
                                         const uint32_t b[2]) {
    asm volatile(
        "mma.sync.aligned.m16n8k16.row.col.f32.bf16.bf16.f32 "
        "{%0,%1,%2,%3}, {%4,%5,%6,%7}, {%8,%9}, {%0,%1,%2,%3};"
        : "+f"(c[0]), "+f"(c[1]), "+f"(c[2]), "+f"(c[3])
        : "r"(a[0]), "r"(a[1]), "r"(a[2]), "r"(a[3]), "r"(b[0]), "r"(b[1]));
}

__global__ __launch_bounds__(256) void gemm_fill_kernel(
    const float* __restrict__ x, const void* __restrict__ ei)
{
    if (blockIdx.x >= G_GEMM) {
        // ------------------ fill path ------------------
        long long start = (long long)(blockIdx.x - G_GEMM) * blockDim.x + threadIdx.x;
        for (long long e = start; e < N_EDGES; e += (long long)G_FILL * 256) {
            int r = (int)edge_at(ei, e);
            int c = (int)edge_at(ei, (long long)N_EDGES + e);
            int pos = atomicAdd(&g_cur[c], 1);
            g_src[pos] = r;
        }
        return;
    }

    // ------------------ gemm path ------------------
    extern __shared__ uint32_t smem[];
    uint32_t* xs_hi = smem;                    // [128][XSP]
    uint32_t* xs_lo = xs_hi + 128 * XSP;
    uint32_t* ws_hi = xs_lo + 128 * XSP;       // [128][WSP]
    uint32_t* ws_lo = ws_hi + 128 * WSP;

    const int tid  = threadIdx.x;
    const int lane = tid & 31;
    const int w    = tid >> 5;
    const int wm   = w & 3;
    const int wn   = w >> 2;
    const int grp  = lane >> 2;
    const int qid  = lane & 3;
    const int row0 = blockIdx.x * 128;

    // Copy precomputed W images (L2-resident) into padded SMEM.
    {
        int r = tid >> 1;
        int h = tid & 1;
        const uint4* sh = (const uint4*)&g_Whi[r * 64 + h * 32];
        const uint4* sl = (const uint4*)&g_Wlo[r * 64 + h * 32];
        uint4* dh = (uint4*)&ws_hi[r * WSP + h * 32];
        uint4* dl = (uint4*)&ws_lo[r * WSP + h * 32];
        #pragma unroll
        for (int i = 0; i < 8; i++) { dh[i] = sh[i]; dl[i] = sl[i]; }
    }

    float acc[2][8][4];
    #pragma unroll
    for (int mt = 0; mt < 2; mt++)
        #pragma unroll
        for (int nt = 0; nt < 8; nt++)
            #pragma unroll
            for (int q = 0; q < 4; q++) acc[mt][nt][q] = 0.0f;

    for (int kc = 0; kc < 4; kc++) {            // K chunk = 32
        #pragma unroll
        for (int i = 0; i < 4; i++) {
            int idx = tid + i * 256;
            int r   = idx >> 3;
            int c4  = idx & 7;
            int gr  = row0 + r;
            float4 v = make_float4(0.f, 0.f, 0.f, 0.f);
            if (gr < N_NODES)
                v = *(const float4*)(x + (size_t)gr * FEAT + kc * 32 + c4 * 4);
            const float vv[4] = {v.x, v.y, v.z, v.w};
            #pragma unroll
            for (int j = 0; j < 2; j++) {
                float a0 = vv[2 * j], a1 = vv[2 * j + 1];
                __nv_bfloat16 h0 = __float2bfloat16(a0);
                __nv_bfloat16 h1 = __float2bfloat16(a1);
                __nv_bfloat16 l0 = __float2bfloat16(a0 - __bfloat162float(h0));
                __nv_bfloat16 l1 = __float2bfloat16(a1 - __bfloat162float(h1));
                xs_hi[r * XSP + c4 * 2 + j] =
                    (uint32_t)__bfloat16_as_ushort(h0) |
                    ((uint32_t)__bfloat16_as_ushort(h1) << 16);
                xs_lo[r * XSP + c4 * 2 + j] =
                    (uint32_t)__bfloat16_as_ushort(l0) |
                    ((uint32_t)__bfloat16_as_ushort(l1) << 16);
            }
        }
        __syncthreads();

        #pragma unroll
        for (int ks = 0; ks < 2; ks++) {
            int xp = ks * 8;
            int wp = kc * 16 + ks * 8;
            uint32_t a_hi[2][4], a_lo[2][4];
            #pragma unroll
            for (int mt = 0; mt < 2; mt++) {
                int r0 = 32 * wm + 16 * mt;
                int i0 = (r0 + grp) * XSP + xp + qid;
                int i1 = (r0 + grp + 8) * XSP + xp + qid;
                a_hi[mt][0] = xs_hi[i0];
                a_hi[mt][1] = xs_hi[i1];
                a_hi[mt][2] = xs_hi[i0 + 4];
                a_hi[mt][3] = xs_hi[i1 + 4];
                a_lo[mt][0] = xs_lo[i0];
                a_lo[mt][1] = xs_lo[i1];
                a_lo[mt][2] = xs_lo[i0 + 4];
                a_lo[mt][3] = xs_lo[i1 + 4];
            }
            #pragma unroll
            for (int nt = 0; nt < 8; nt++) {
                int nb = (64 * wn + 8 * nt + grp) * WSP + wp + qid;
                uint32_t b_hi[2], b_lo[2];
                b_hi[0] = ws_hi[nb];
                b_hi[1] = ws_hi[nb + 4];
                b_lo[0] = ws_lo[nb];
                b_lo[1] = ws_lo[nb + 4];
                #pragma unroll
                for (int mt = 0; mt < 2; mt++) {
                    mma_bf16(acc[mt][nt], a_lo[mt], b_hi);
                    mma_bf16(acc[mt][nt], a_hi[mt], b_lo);
                    mma_bf16(acc[mt][nt], a_hi[mt], b_hi);
                }
            }
        }
        __syncthreads();
    }

    // Epilogue: write fp16 xw.
    #pragma unroll
    for (int mt = 0; mt < 2; mt++) {
        int r0 = row0 + 32 * wm + 16 * mt + grp;
        #pragma unroll
        for (int nt = 0; nt < 8; nt++) {
            int cb = 64 * wn + 8 * nt + 2 * qid;
            if (r0 < N_NODES)
                *(__half2*)(g_xw + (size_t)r0 * FEAT + cb) =
                    __floats2half2_rn(acc[mt][nt][0], acc[mt][nt][1]);
            if (r0 + 8 < N_NODES)
                *(__half2*)(g_xw + (size_t)(r0 + 8) * FEAT + cb) =
                    __floats2half2_rn(acc[mt][nt][2], acc[mt][nt][3]);
        }
    }
}

// ---------------------------------------------------------------------------
// Gather: one warp per target node; fp16 row reads (8B/lane), fp32 accum.
// ---------------------------------------------------------------------------
__device__ __forceinline__ float4 load_row4(long long node, int lane) {
    uint2 u = *((const uint2*)(g_xw + (size_t)node * FEAT) + lane);
    __half2 p0 = *reinterpret_cast<__half2*>(&u.x);
    __half2 p1 = *reinterpret_cast<__half2*>(&u.y);
    float2 f0 = __half22float2(p0);
    float2 f1 = __half22float2(p1);
    return make_float4(f0.x, f0.y, f1.x, f1.y);
}

__global__ __launch_bounds__(256) void gather_kernel(
    const float* __restrict__ b, float* __restrict__ out)
{
    int node = blockIdx.x * 8 + (threadIdx.x >> 5);
    if (node >= N_NODES) return;
    int lane = threadIdx.x & 31;

    float dc = g_dis[node];
    float d2 = dc * dc;

    float4 acc = load_row4(node, lane);
    acc.x *= d2; acc.y *= d2; acc.z *= d2; acc.w *= d2;   // self-loop

    int base = g_base[node];
    int deg  = g_degi[node];

    int i = 0;
    for (; i + 1 < deg; i += 2) {
        int r0 = g_src[base + i];
        int r1 = g_src[base + i + 1];
        float n0 = g_dis[r0] * dc;
        float n1 = g_dis[r1] * dc;
        float4 v0 = load_row4(r0, lane);
        float4 v1 = load_row4(r1, lane);
        acc.x = fmaf(v0.x, n0, acc.x); acc.y = fmaf(v0.y, n0, acc.y);
        acc.z = fmaf(v0.z, n0, acc.z); acc.w = fmaf(v0.w, n0, acc.w);
        acc.x = fmaf(v1.x, n1, acc.x); acc.y = fmaf(v1.y, n1, acc.y);
        acc.z = fmaf(v1.z, n1, acc.z); acc.w = fmaf(v1.w, n1, acc.w);
    }
    if (i < deg) {
        int r0 = g_src[base + i];
        float n0 = g_dis[r0] * dc;
        float4 v0 = load_row4(r0, lane);
        acc.x = fmaf(v0.x, n0, acc.x); acc.y = fmaf(v0.y, n0, acc.y);
        acc.z = fmaf(v0.z, n0, acc.z); acc.w = fmaf(v0.w, n0, acc.w);
    }

    float4 bb = ((const float4*)b)[lane];
    acc.x += bb.x; acc.y += bb.y; acc.z += bb.z; acc.w += bb.w;
    ((float4*)(out + (size_t)node * FEAT))[lane] = acc;
}

// ---------------------------------------------------------------------------
extern "C" void kernel_launch(void* const* d_in, const int* in_sizes, int n_in,
                              void* d_out, int out_size)
{
    const float* x  = (const float*)d_in[0];
    const float* W  = (const float*)d_in[1];
    const float* b  = (const float*)d_in[2];
    const void*  ei = d_in[3];
    float* out = (float*)d_out;

    cudaFuncSetAttribute(gemm_fill_kernel,
                         cudaFuncAttributeMaxDynamicSharedMemorySize, GEMM_SMEM);

    init_wprep_kernel<<<391 + 32, 256>>>((const unsigned int*)ei, W);
    hist_kernel<<<(N_EDGES + 255) / 256, 256>>>(ei);
    scan1_kernel<<<N_SBLK, SCAN_BLK>>>();
    scan23_kernel<<<(N_NODES + 255) / 256, 256>>>();
    gemm_fill_kernel<<<G_GEMM + G_FILL, 256, GEMM_SMEM>>>(x, ei);
    gather_kernel<<<(N_NODES + 7) / 8, 256>>>(b, out);
}